// round 1
// baseline (speedup 1.0000x reference)
#include <cuda_runtime.h>
#include <math.h>

// Problem constants
#define BB 64
#define LL 512
#define EE 512
#define HH 1024

// ---------------- static device scratch (no allocations allowed) ----------------
__device__ float g_word[32768 * 512];            // embedded tokens  [B*L, E]
__device__ float g_pre[(size_t)32768 * 2048];    // GEMM pre-activations (leaf: z|h, internal: z|r)
__device__ float g_G[(size_t)16384 * 2048];      // [r*hl | r*hr]
__device__ float g_zbuf[(size_t)16384 * 1024];   // z gate
__device__ float g_htpre[(size_t)16384 * 1024];  // h_tilde pre-activation
__device__ float g_h0[(size_t)32768 * 1024];     // ping
__device__ float g_h1[(size_t)16384 * 1024];     // pong
__device__ float g_wleaf[512 * 2048];            // [W_z | W_h]
__device__ float g_w1[2048 * 2048];              // [[U_zl U_rl],[U_zr U_rr]]
__device__ float g_w2[2048 * 1024];              // [[U_hl],[U_hr]]
__device__ float g_bias[3 * 1024];               // bz+bzl+bzr | br+brl+brr | bh+bhl+bhr

__device__ __forceinline__ float sigmoidf_(float x) { return 1.0f / (1.0f + expf(-x)); }

// ---------------- prep kernels ----------------
__global__ void build_bias_k(const float* bz, const float* bzl, const float* bzr,
                             const float* br, const float* brl, const float* brr,
                             const float* bh, const float* bhl, const float* bhr,
                             float* out) {
    int j = blockIdx.x * blockDim.x + threadIdx.x;
    if (j < 1024) {
        out[j]        = bz[j] + bzl[j] + bzr[j];
        out[1024 + j] = br[j] + brl[j] + brr[j];
        out[2048 + j] = bh[j] + bhl[j] + bhr[j];
    }
}

__global__ void build_wleaf_k(const float* Wz, const float* Wh, float* W) {
    int idx = blockIdx.x * blockDim.x + threadIdx.x;  // 512*2048
    if (idx < 512 * 2048) {
        int k = idx >> 11, j = idx & 2047;
        W[idx] = (j < 1024) ? Wz[k * 1024 + j] : Wh[k * 1024 + (j - 1024)];
    }
}

__global__ void build_w1_k(const float* Uzl, const float* Uzr,
                           const float* Url, const float* Urr, float* W) {
    int idx = blockIdx.x * blockDim.x + threadIdx.x;  // 2048*2048
    if (idx < 2048 * 2048) {
        int k = idx >> 11, j = idx & 2047;
        const float* src = (k < 1024) ? ((j < 1024) ? Uzl : Url)
                                      : ((j < 1024) ? Uzr : Urr);
        W[idx] = src[(k & 1023) * 1024 + (j & 1023)];
    }
}

__global__ void build_w2_k(const float* Uhl, const float* Uhr, float* W) {
    int idx = blockIdx.x * blockDim.x + threadIdx.x;  // 2048*1024
    if (idx < 2048 * 1024) {
        int k = idx >> 10, j = idx & 1023;
        W[idx] = (k < 1024) ? Uhl[k * 1024 + j] : Uhr[(k - 1024) * 1024 + j];
    }
}

__global__ void gather_k(const int* tokens, const float* emb, float* word) {
    int idx = blockIdx.x * blockDim.x + threadIdx.x;  // 32768 * 128 float4
    if (idx < 32768 * 128) {
        int i = idx >> 7, e4 = idx & 127;
        int t = tokens[i];
        reinterpret_cast<float4*>(word)[idx] =
            reinterpret_cast<const float4*>(emb + (size_t)t * 512)[e4];
    }
}

// ---------------- fp32 SIMT GEMM: C[M,N] = A[M,K] @ B[K,N] ----------------
// 128x128 block tile, BK=16, 256 threads, 8x8 per thread.
// Requires N%128==0 and K%16==0 (true for all call sites). M guarded.
#define GBM 128
#define GBN 128
#define GBK 16

__global__ __launch_bounds__(256) void gemm_f32(const float* __restrict__ A,
                                                const float* __restrict__ B,
                                                float* __restrict__ C,
                                                int M, int N, int K) {
    __shared__ float As[GBK][GBM + 4];
    __shared__ float Bs[GBK][GBN];

    const int tid = threadIdx.x;
    const int tx = tid & 15;        // 0..15 -> N
    const int ty = tid >> 4;        // 0..15 -> M
    const int bx = blockIdx.x;      // N tile
    const int by = blockIdx.y;      // M tile

    const int aRow = tid >> 2;      // 0..63
    const int aCol4 = tid & 3;      // 0..3
    const int bRow = tid >> 5;      // 0..7
    const int bCol4 = tid & 31;     // 0..31

    float acc[8][8];
#pragma unroll
    for (int i = 0; i < 8; i++)
#pragma unroll
        for (int j = 0; j < 8; j++) acc[i][j] = 0.0f;

    for (int kt = 0; kt < K; kt += GBK) {
        // load A tile (transposed into smem)
#pragma unroll
        for (int s = 0; s < 2; s++) {
            int r = aRow + s * 64;
            int grow = by * GBM + r;
            float4 v = make_float4(0.f, 0.f, 0.f, 0.f);
            if (grow < M)
                v = *reinterpret_cast<const float4*>(&A[(size_t)grow * K + kt + aCol4 * 4]);
            As[aCol4 * 4 + 0][r] = v.x;
            As[aCol4 * 4 + 1][r] = v.y;
            As[aCol4 * 4 + 2][r] = v.z;
            As[aCol4 * 4 + 3][r] = v.w;
        }
        // load B tile
#pragma unroll
        for (int s = 0; s < 2; s++) {
            int r = bRow + s * 8;
            float4 v = *reinterpret_cast<const float4*>(
                &B[(size_t)(kt + r) * N + bx * GBN + bCol4 * 4]);
            *reinterpret_cast<float4*>(&Bs[r][bCol4 * 4]) = v;
        }
        __syncthreads();

#pragma unroll
        for (int k = 0; k < GBK; k++) {
            float a[8], b[8];
            *reinterpret_cast<float4*>(&a[0]) = *reinterpret_cast<const float4*>(&As[k][ty * 8]);
            *reinterpret_cast<float4*>(&a[4]) = *reinterpret_cast<const float4*>(&As[k][ty * 8 + 4]);
            *reinterpret_cast<float4*>(&b[0]) = *reinterpret_cast<const float4*>(&Bs[k][tx * 8]);
            *reinterpret_cast<float4*>(&b[4]) = *reinterpret_cast<const float4*>(&Bs[k][tx * 8 + 4]);
#pragma unroll
            for (int i = 0; i < 8; i++)
#pragma unroll
                for (int j = 0; j < 8; j++) acc[i][j] = fmaf(a[i], b[j], acc[i][j]);
        }
        __syncthreads();
    }

#pragma unroll
    for (int i = 0; i < 8; i++) {
        int grow = by * GBM + ty * 8 + i;
        if (grow < M) {
            float4 v0 = make_float4(acc[i][0], acc[i][1], acc[i][2], acc[i][3]);
            float4 v1 = make_float4(acc[i][4], acc[i][5], acc[i][6], acc[i][7]);
            *reinterpret_cast<float4*>(&C[(size_t)grow * N + bx * GBN + tx * 8]) = v0;
            *reinterpret_cast<float4*>(&C[(size_t)grow * N + bx * GBN + tx * 8 + 4]) = v1;
        }
    }
}

// ---------------- elementwise kernels ----------------
// Leaf: h = (1-z)*tanh(ht_pre)  (hl=hr=0 so r never matters)
__global__ void ew_leaf_k(const float* __restrict__ pre, const float* __restrict__ bias,
                          float* __restrict__ h) {
    int idx = blockIdx.x * blockDim.x + threadIdx.x;
    if (idx < 32768 * 1024) {
        int i = idx >> 10, j = idx & 1023;
        float z = sigmoidf_(pre[(size_t)i * 2048 + j] + bias[j]);
        float ht = tanhf(pre[(size_t)i * 2048 + 1024 + j] + bias[2048 + j]);
        h[idx] = (1.0f - z) * ht;
    }
}

// Internal stage 1: z, r gates; G = [r*hl | r*hr]
__global__ void ew1_k(const float* __restrict__ pre, const float* __restrict__ X,
                      const float* __restrict__ bias, float* __restrict__ z,
                      float* __restrict__ G, int rows) {
    int idx = blockIdx.x * blockDim.x + threadIdx.x;
    if (idx < rows * 1024) {
        int i = idx >> 10, j = idx & 1023;
        size_t base = (size_t)i * 2048;
        float zz = sigmoidf_(pre[base + j] + bias[j]);
        float rr = sigmoidf_(pre[base + 1024 + j] + bias[1024 + j]);
        z[idx] = zz;
        G[base + j] = rr * X[base + j];
        G[base + 1024 + j] = rr * X[base + 1024 + j];
    }
}

// Internal stage 2: h = z*(hl+hr) + (1-z)*tanh(ht_pre)
__global__ void ew2_k(const float* __restrict__ X, const float* __restrict__ z,
                      const float* __restrict__ htpre, const float* __restrict__ bias,
                      float* __restrict__ hout, int rows) {
    int idx = blockIdx.x * blockDim.x + threadIdx.x;
    if (idx < rows * 1024) {
        int i = idx >> 10, j = idx & 1023;
        size_t base = (size_t)i * 2048;
        float ht = tanhf(htpre[idx] + bias[2048 + j]);
        float zz = z[idx];
        hout[idx] = zz * (X[base + j] + X[base + 1024 + j]) + (1.0f - zz) * ht;
    }
}

// ---------------- launch ----------------
extern "C" void kernel_launch(void* const* d_in, const int* in_sizes, int n_in,
                              void* d_out, int out_size) {
    const int*   tokens = (const int*)d_in[0];
    const float* emb  = (const float*)d_in[1];
    const float* W_z  = (const float*)d_in[2];
    const float* b_z  = (const float*)d_in[3];
    const float* U_zl = (const float*)d_in[4];
    const float* b_zl = (const float*)d_in[5];
    const float* U_zr = (const float*)d_in[6];
    const float* b_zr = (const float*)d_in[7];
    const float* W_r  = (const float*)d_in[8];
    const float* b_r  = (const float*)d_in[9];
    const float* U_rl = (const float*)d_in[10];
    const float* b_rl = (const float*)d_in[11];
    const float* U_rr = (const float*)d_in[12];
    const float* b_rr = (const float*)d_in[13];
    const float* W_h  = (const float*)d_in[14];
    const float* b_h  = (const float*)d_in[15];
    const float* U_hl = (const float*)d_in[16];
    const float* b_hl = (const float*)d_in[17];
    const float* U_hr = (const float*)d_in[18];
    const float* b_hr = (const float*)d_in[19];
    (void)W_r; (void)in_sizes; (void)n_in; (void)out_size;

    float *word, *pre, *G, *zb, *htp, *h0, *h1, *wl, *w1, *w2, *bias;
    cudaGetSymbolAddress((void**)&word, g_word);
    cudaGetSymbolAddress((void**)&pre,  g_pre);
    cudaGetSymbolAddress((void**)&G,    g_G);
    cudaGetSymbolAddress((void**)&zb,   g_zbuf);
    cudaGetSymbolAddress((void**)&htp,  g_htpre);
    cudaGetSymbolAddress((void**)&h0,   g_h0);
    cudaGetSymbolAddress((void**)&h1,   g_h1);
    cudaGetSymbolAddress((void**)&wl,   g_wleaf);
    cudaGetSymbolAddress((void**)&w1,   g_w1);
    cudaGetSymbolAddress((void**)&w2,   g_w2);
    cudaGetSymbolAddress((void**)&bias, g_bias);

    // prep
    build_bias_k<<<4, 256>>>(b_z, b_zl, b_zr, b_r, b_rl, b_rr, b_h, b_hl, b_hr, bias);
    build_wleaf_k<<<(512 * 2048) / 256, 256>>>(W_z, W_h, wl);
    build_w1_k<<<(2048 * 2048) / 256, 256>>>(U_zl, U_zr, U_rl, U_rr, w1);
    build_w2_k<<<(2048 * 1024) / 256, 256>>>(U_hl, U_hr, w2);
    gather_k<<<(32768 * 128) / 256, 256>>>(tokens, emb, word);

    // leaf: [32768,512] @ [512,2048] -> pre (z|h), then h0
    gemm_f32<<<dim3(2048 / GBN, 32768 / GBM), 256>>>(word, wl, pre, 32768, 2048, 512);
    ew_leaf_k<<<(32768 * 1024) / 256, 256>>>(pre, bias, h0);

    // internal levels: pairs are adjacent rows -> X = hcur viewed as [rows, 2048]
    float* hcur = h0;
    float* nxt = h1;
    for (int m = 512; m > 1; m >>= 1) {
        int n = m >> 1;
        int rows = BB * n;
        gemm_f32<<<dim3(2048 / GBN, (rows + GBM - 1) / GBM), 256>>>(hcur, w1, pre, rows, 2048, 2048);
        ew1_k<<<(rows * 1024 + 255) / 256, 256>>>(pre, hcur, bias, zb, G, rows);
        gemm_f32<<<dim3(1024 / GBN, (rows + GBM - 1) / GBM), 256>>>(G, w2, htp, rows, 1024, 2048);
        float* out = (n == 1) ? (float*)d_out : nxt;
        ew2_k<<<(rows * 1024 + 255) / 256, 256>>>(hcur, zb, htp, bias, out, rows);
        float* t = hcur; hcur = out; nxt = t;
    }
}

// round 11
// speedup vs baseline: 6.5583x; 6.5583x over previous
#include <cuda_runtime.h>
#include <cuda_fp16.h>
#include <math.h>
#include <stdint.h>

// Problem constants
#define BB 64
#define LL 512
#define EE 512
#define HH 1024

// ---------------- static device scratch ----------------
__device__ __half g_word[(size_t)32768 * 512];    // embedded tokens  [B*L, E] fp16
__device__ float  g_pre[(size_t)32768 * 2048];    // GEMM pre-activations (fp32)
__device__ __half g_G[(size_t)16384 * 2048];      // [r*hl | r*hr] fp16
__device__ float  g_zbuf[(size_t)16384 * 1024];   // z gate fp32
__device__ float  g_htpre[(size_t)16384 * 1024];  // h_tilde pre-activation fp32
__device__ __half g_h0[(size_t)32768 * 1024];     // ping fp16
__device__ __half g_h1[(size_t)16384 * 1024];     // pong fp16
__device__ __half g_wleafT[(size_t)2048 * 512];   // [W_z|W_h]^T  [N=2048][K=512]
__device__ __half g_w1T[(size_t)2048 * 2048];     // [[Uzl Url],[Uzr Urr]]^T [N=2048][K=2048]
__device__ __half g_w2T[(size_t)1024 * 2048];     // [[Uhl],[Uhr]]^T [N=1024][K=2048]
__device__ float  g_bias[3 * 1024];               // z | r | h fused biases

__device__ __forceinline__ float sigmoidf_(float x) { return 1.0f / (1.0f + expf(-x)); }

__device__ __forceinline__ uint32_t smem_u32(const void* p) {
    return (uint32_t)__cvta_generic_to_shared((void*)p);
}

#define SWZ128(off) ((off) ^ (((off) >> 3) & 0x70))

// cp.async 16B (sm_80+, non-arch-specific)
__device__ __forceinline__ void cp_async16(uint32_t saddr, const void* gaddr) {
    asm volatile("cp.async.cg.shared.global [%0], [%1], 16;" :: "r"(saddr), "l"(gaddr));
}
#define CP_COMMIT() asm volatile("cp.async.commit_group;" ::: "memory")
#define CP_WAIT1()  asm volatile("cp.async.wait_group 1;" ::: "memory")
#define CP_WAIT0()  asm volatile("cp.async.wait_group 0;" ::: "memory")

__device__ __forceinline__ void ldsm_x4(uint32_t& r0, uint32_t& r1, uint32_t& r2, uint32_t& r3,
                                        uint32_t addr) {
    asm volatile("ldmatrix.sync.aligned.m8n8.x4.shared.b16 {%0,%1,%2,%3}, [%4];"
                 : "=r"(r0), "=r"(r1), "=r"(r2), "=r"(r3) : "r"(addr));
}

__device__ __forceinline__ void mma16816(float* c, uint32_t a0, uint32_t a1, uint32_t a2,
                                         uint32_t a3, uint32_t b0, uint32_t b1) {
    asm volatile(
        "mma.sync.aligned.m16n8k16.row.col.f32.f16.f16.f32 "
        "{%0,%1,%2,%3}, {%4,%5,%6,%7}, {%8,%9}, {%0,%1,%2,%3};"
        : "+f"(c[0]), "+f"(c[1]), "+f"(c[2]), "+f"(c[3])
        : "r"(a0), "r"(a1), "r"(a2), "r"(a3), "r"(b0), "r"(b1));
}

// ---------------- mma.sync fp16 GEMM: C[M,N] = A[M,K] @ Bt[N,K]^T ----------------
// CTA tile 128x128, BK=64 halves (128B SW128 rows), cp.async double buffered.
// 8 warps: warp (wm 0..3, wn 0..1) computes 32x64.
#define TILE_BYTES 16384
#define SMEM_BYTES (4 * TILE_BYTES)

__global__ __launch_bounds__(256) void gemm_mma(const __half* __restrict__ A,
                                                const __half* __restrict__ Bt,
                                                float* __restrict__ C,
                                                int M, int K, int N) {
    extern __shared__ __align__(1024) char smem[];
    char* Abuf[2] = { smem, smem + TILE_BYTES };
    char* Bbuf[2] = { smem + 2 * TILE_BYTES, smem + 3 * TILE_BYTES };

    const int tid = threadIdx.x;
    const int warp = tid >> 5, lane = tid & 31;
    const int wm = warp & 3;   // 0..3 -> 32-row slice
    const int wn = warp >> 2;  // 0..1 -> 64-col slice
    const int bx = blockIdx.x; // N/128
    const int by = blockIdx.y; // M/128

    const size_t a_row0 = (size_t)by * 128;
    const size_t b_row0 = (size_t)bx * 128;
    const int NC = K >> 6;

    float acc[2][8][4];
#pragma unroll
    for (int i = 0; i < 2; i++)
#pragma unroll
        for (int j = 0; j < 8; j++)
#pragma unroll
            for (int k = 0; k < 4; k++) acc[i][j][k] = 0.0f;

    // per-thread load slots: 4 chunks A + 4 chunks B (16B each)
    const int lrow = tid >> 3;        // base row within 128 handled per i-step
    const int lch = tid & 7;          // 16B chunk within 128B row

    // issue loads for chunk c into buffer s
    auto issue = [&](int c, int s) {
        const int kt = c << 6;
#pragma unroll
        for (int i = 0; i < 4; ++i) {
            int row = lrow + i * 32;
            const __half* g = A + (a_row0 + row) * K + kt + lch * 8;
            cp_async16(smem_u32(Abuf[s] + SWZ128(row * 128 + lch * 16)), g);
        }
#pragma unroll
        for (int i = 0; i < 4; ++i) {
            int row = lrow + i * 32;
            const __half* g = Bt + (b_row0 + row) * K + kt + lch * 8;
            cp_async16(smem_u32(Bbuf[s] + SWZ128(row * 128 + lch * 16)), g);
        }
        CP_COMMIT();
    };

    issue(0, 0);

    for (int c = 0; c < NC; ++c) {
        const int s = c & 1;
        if (c + 1 < NC) {
            issue(c + 1, s ^ 1);
            CP_WAIT1();
        } else {
            CP_WAIT0();
        }
        __syncthreads();

        const uint32_t Abase = smem_u32(Abuf[s]);
        const uint32_t Bbase = smem_u32(Bbuf[s]);
        // A frag addr: row = wm*32 + mt*16 + lane%16, byte col = ks*32 + (lane/16)*16
        // B frag addr: row = wn*64 + bt*16 + lane%8 + (lane/16)*8, byte col = ks*32 + ((lane/8)%2)*16
        const int arow = wm * 32 + (lane & 15);
        const int acol = (lane >> 4) << 4;
        const int brow = wn * 64 + (lane & 7) + ((lane >> 4) << 3);
        const int bcol = ((lane >> 3) & 1) << 4;

#pragma unroll
        for (int ks = 0; ks < 4; ++ks) {
            uint32_t a[2][4];
#pragma unroll
            for (int mt = 0; mt < 2; ++mt) {
                uint32_t addr = Abase + SWZ128((arow + mt * 16) * 128 + ks * 32 + acol);
                ldsm_x4(a[mt][0], a[mt][1], a[mt][2], a[mt][3], addr);
            }
            uint32_t b[4][4];
#pragma unroll
            for (int bt = 0; bt < 4; ++bt) {
                uint32_t addr = Bbase + SWZ128((brow + bt * 16) * 128 + ks * 32 + bcol);
                ldsm_x4(b[bt][0], b[bt][1], b[bt][2], b[bt][3], addr);
            }
#pragma unroll
            for (int mt = 0; mt < 2; ++mt)
#pragma unroll
                for (int nt = 0; nt < 8; ++nt) {
                    const int g = nt >> 1, p = (nt & 1) << 1;
                    mma16816(acc[mt][nt], a[mt][0], a[mt][1], a[mt][2], a[mt][3],
                             b[g][p], b[g][p + 1]);
                }
        }
        __syncthreads();
    }

    // epilogue: fragment (mt, nt): rows by*128+wm*32+mt*16+lane/4 (+8), cols bx*128+wn*64+nt*8+(lane%4)*2
    const int rbase = by * 128 + wm * 32 + (lane >> 2);
    const int cbase = bx * 128 + wn * 64 + (lane & 3) * 2;
#pragma unroll
    for (int mt = 0; mt < 2; ++mt) {
#pragma unroll
        for (int nt = 0; nt < 8; ++nt) {
            int r0 = rbase + mt * 16;
            int cc = cbase + nt * 8;
            if (r0 < M)
                *reinterpret_cast<float2*>(C + (size_t)r0 * N + cc) =
                    make_float2(acc[mt][nt][0], acc[mt][nt][1]);
            if (r0 + 8 < M)
                *reinterpret_cast<float2*>(C + (size_t)(r0 + 8) * N + cc) =
                    make_float2(acc[mt][nt][2], acc[mt][nt][3]);
        }
    }
}

// ---------------- prep kernels ----------------
__global__ void build_bias_k(const float* bz, const float* bzl, const float* bzr,
                             const float* br, const float* brl, const float* brr,
                             const float* bh, const float* bhl, const float* bhr,
                             float* out) {
    int j = blockIdx.x * blockDim.x + threadIdx.x;
    if (j < 1024) {
        out[j]        = bz[j] + bzl[j] + bzr[j];
        out[1024 + j] = br[j] + brl[j] + brr[j];
        out[2048 + j] = bh[j] + bhl[j] + bhr[j];
    }
}

// transpose + fp16 convert: out[n][k] = src[k][n]
__global__ void trans_wleaf(const float* Wz, const float* Wh, __half* out) {
    __shared__ float t[32][33];
    int k0 = blockIdx.x * 32, n0 = blockIdx.y * 32;
    int tx = threadIdx.x, ty = threadIdx.y;
    const float* src = (n0 < 1024) ? Wz : Wh;
    int nn = n0 & 1023;
    t[ty][tx] = src[(size_t)(k0 + ty) * 1024 + nn + tx];
    __syncthreads();
    out[(size_t)(n0 + ty) * 512 + k0 + tx] = __float2half_rn(t[tx][ty]);
}

__global__ void trans_w1(const float* Uzl, const float* Uzr,
                         const float* Url, const float* Urr, __half* out) {
    __shared__ float t[32][33];
    int k0 = blockIdx.x * 32, n0 = blockIdx.y * 32;
    int tx = threadIdx.x, ty = threadIdx.y;
    const float* src = (k0 < 1024) ? ((n0 < 1024) ? Uzl : Url)
                                   : ((n0 < 1024) ? Uzr : Urr);
    t[ty][tx] = src[(size_t)((k0 & 1023) + ty) * 1024 + (n0 & 1023) + tx];
    __syncthreads();
    out[(size_t)(n0 + ty) * 2048 + k0 + tx] = __float2half_rn(t[tx][ty]);
}

__global__ void trans_w2(const float* Uhl, const float* Uhr, __half* out) {
    __shared__ float t[32][33];
    int k0 = blockIdx.x * 32, n0 = blockIdx.y * 32;
    int tx = threadIdx.x, ty = threadIdx.y;
    const float* src = (k0 < 1024) ? Uhl : Uhr;
    t[ty][tx] = src[(size_t)((k0 & 1023) + ty) * 1024 + n0 + tx];
    __syncthreads();
    out[(size_t)(n0 + ty) * 2048 + k0 + tx] = __float2half_rn(t[tx][ty]);
}

__global__ void gather_k(const int* tokens, const float* emb, __half* word) {
    int idx = blockIdx.x * blockDim.x + threadIdx.x;  // 32768*128 groups of 4
    if (idx < 32768 * 128) {
        int i = idx >> 7, e4 = idx & 127;
        int t = tokens[i];
        float4 v = reinterpret_cast<const float4*>(emb + (size_t)t * 512)[e4];
        __half2 h0 = __floats2half2_rn(v.x, v.y);
        __half2 h1 = __floats2half2_rn(v.z, v.w);
        reinterpret_cast<__half2*>(word)[2 * idx]     = h0;
        reinterpret_cast<__half2*>(word)[2 * idx + 1] = h1;
    }
}

// ---------------- elementwise kernels ----------------
__global__ void ew_leaf_k(const float* __restrict__ pre, const float* __restrict__ bias,
                          __half* __restrict__ h) {
    int idx = blockIdx.x * blockDim.x + threadIdx.x;
    if (idx < 32768 * 1024) {
        int i = idx >> 10, j = idx & 1023;
        size_t base = (size_t)i * 2048;
        float z = sigmoidf_(pre[base + j] + bias[j]);
        float ht = tanhf(pre[base + 1024 + j] + bias[2048 + j]);
        h[idx] = __float2half_rn((1.0f - z) * ht);
    }
}

__global__ void ew1_k(const float* __restrict__ pre, const __half* __restrict__ X,
                      const float* __restrict__ bias, float* __restrict__ z,
                      __half* __restrict__ G, int rows) {
    int idx = blockIdx.x * blockDim.x + threadIdx.x;
    if (idx < rows * 1024) {
        int i = idx >> 10, j = idx & 1023;
        size_t base = (size_t)i * 2048;
        float zz = sigmoidf_(pre[base + j] + bias[j]);
        float rr = sigmoidf_(pre[base + 1024 + j] + bias[1024 + j]);
        z[idx] = zz;
        float hl = __half2float(X[base + j]);
        float hr = __half2float(X[base + 1024 + j]);
        G[base + j] = __float2half_rn(rr * hl);
        G[base + 1024 + j] = __float2half_rn(rr * hr);
    }
}

__global__ void ew2_k(const __half* __restrict__ X, const float* __restrict__ z,
                      const float* __restrict__ htpre, const float* __restrict__ bias,
                      void* __restrict__ hout, int rows, int is_final) {
    int idx = blockIdx.x * blockDim.x + threadIdx.x;
    if (idx < rows * 1024) {
        int i = idx >> 10, j = idx & 1023;
        size_t base = (size_t)i * 2048;
        float ht = tanhf(htpre[idx] + bias[2048 + j]);
        float zz = z[idx];
        float hl = __half2float(X[base + j]);
        float hr = __half2float(X[base + 1024 + j]);
        float val = zz * (hl + hr) + (1.0f - zz) * ht;
        if (is_final) ((float*)hout)[idx] = val;
        else          ((__half*)hout)[idx] = __float2half_rn(val);
    }
}

// ---------------- launch ----------------
extern "C" void kernel_launch(void* const* d_in, const int* in_sizes, int n_in,
                              void* d_out, int out_size) {
    const int*   tokens = (const int*)d_in[0];
    const float* emb  = (const float*)d_in[1];
    const float* W_z  = (const float*)d_in[2];
    const float* b_z  = (const float*)d_in[3];
    const float* U_zl = (const float*)d_in[4];
    const float* b_zl = (const float*)d_in[5];
    const float* U_zr = (const float*)d_in[6];
    const float* b_zr = (const float*)d_in[7];
    const float* W_r  = (const float*)d_in[8];
    const float* b_r  = (const float*)d_in[9];
    const float* U_rl = (const float*)d_in[10];
    const float* b_rl = (const float*)d_in[11];
    const float* U_rr = (const float*)d_in[12];
    const float* b_rr = (const float*)d_in[13];
    const float* W_h  = (const float*)d_in[14];
    const float* b_h  = (const float*)d_in[15];
    const float* U_hl = (const float*)d_in[16];
    const float* b_hl = (const float*)d_in[17];
    const float* U_hr = (const float*)d_in[18];
    const float* b_hr = (const float*)d_in[19];
    (void)W_r; (void)in_sizes; (void)n_in; (void)out_size;

    __half *word, *G, *h0, *h1, *wlT, *w1T, *w2T;
    float *pre, *zb, *htp, *bias;
    cudaGetSymbolAddress((void**)&word, g_word);
    cudaGetSymbolAddress((void**)&pre,  g_pre);
    cudaGetSymbolAddress((void**)&G,    g_G);
    cudaGetSymbolAddress((void**)&zb,   g_zbuf);
    cudaGetSymbolAddress((void**)&htp,  g_htpre);
    cudaGetSymbolAddress((void**)&h0,   g_h0);
    cudaGetSymbolAddress((void**)&h1,   g_h1);
    cudaGetSymbolAddress((void**)&wlT,  g_wleafT);
    cudaGetSymbolAddress((void**)&w1T,  g_w1T);
    cudaGetSymbolAddress((void**)&w2T,  g_w2T);
    cudaGetSymbolAddress((void**)&bias, g_bias);

    cudaFuncSetAttribute(gemm_mma, cudaFuncAttributeMaxDynamicSharedMemorySize, SMEM_BYTES);

    // prep
    build_bias_k<<<4, 256>>>(b_z, b_zl, b_zr, b_r, b_rl, b_rr, b_h, b_hl, b_hr, bias);
    dim3 tb(32, 32);
    trans_wleaf<<<dim3(16, 64), tb>>>(W_z, W_h, wlT);
    trans_w1<<<dim3(64, 64), tb>>>(U_zl, U_zr, U_rl, U_rr, w1T);
    trans_w2<<<dim3(64, 32), tb>>>(U_hl, U_hr, w2T);
    gather_k<<<(32768 * 128) / 256, 256>>>(tokens, emb, word);

    // leaf: [32768,512] @ wleafT^T -> pre[32768,2048]
    gemm_mma<<<dim3(2048 / 128, 32768 / 128), 256, SMEM_BYTES>>>(word, wlT, pre, 32768, 512, 2048);
    ew_leaf_k<<<(32768 * 1024) / 256, 256>>>(pre, bias, h0);

    // internal levels
    __half* hcur = h0;
    __half* nxt = h1;
    for (int m = 512; m > 1; m >>= 1) {
        int n = m >> 1;
        int rows = BB * n;
        int gridM = (rows + 127) / 128;
        gemm_mma<<<dim3(2048 / 128, gridM), 256, SMEM_BYTES>>>(hcur, w1T, pre, rows, 2048, 2048);
        ew1_k<<<(rows * 1024 + 255) / 256, 256>>>(pre, hcur, bias, zb, G, rows);
        gemm_mma<<<dim3(1024 / 128, gridM), 256, SMEM_BYTES>>>(G, w2T, htp, rows, 2048, 1024);
        int is_final = (n == 1);
        void* out = is_final ? d_out : (void*)nxt;
        ew2_k<<<(rows * 1024 + 255) / 256, 256>>>(hcur, zb, htp, bias, out, rows, is_final);
        if (!is_final) { __half* t = hcur; hcur = nxt; nxt = t; }
    }
}